// round 2
// baseline (speedup 1.0000x reference)
#include <cuda_runtime.h>

#define T_TOTAL 262144
#define NF 64
#define ROWS 256
#define TILES_PER_BLOCK 4

__global__ void __launch_bounds__(256, 8)
ma_kernel(const float* __restrict__ x, float* __restrict__ out) {
    const int t    = threadIdx.x;
    const int f    = t & (NF - 1);
    const int tile = blockIdx.x * TILES_PER_BLOCK + (t >> 6);
    const int r0   = tile * ROWS;

    const float* xc = x + f;
    float*       oc = out + f;

    float s7 = 0.f, s30 = 0.f, s90 = 0.f;

    // Initialize running window sums from the 90-row halo above this tile.
    // For r0 == 0 there is no halo (implicit zeros).
    if (r0 > 0) {
        #pragma unroll 10
        for (int k = 1; k <= 90; k++) {
            float v = xc[(size_t)(r0 - k) * NF];
            s90 += v;
            if (k <= 30) s30 += v;
            if (k <= 7)  s7  += v;
        }
    }

    const float inv7  = 1.0f / 7.0f;
    const float inv30 = 1.0f / 30.0f;
    const float inv90 = 1.0f / 90.0f;

    int i   = r0;
    int end = r0 + ROWS;

    if (r0 == 0) {
        // Careful region: rows 0..89 need expanding-mean divisors and
        // zero-padded lags. Only the first tile ever runs this.
        for (; i < 90; i++) {
            float v = xc[(size_t)i * NF];
            s7 += v; s30 += v; s90 += v;
            if (i >= 7)  s7  -= xc[(size_t)(i - 7)  * NF];
            if (i >= 30) s30 -= xc[(size_t)(i - 30) * NF];
            // i >= 90 never happens here
            float d7  = (i >= 6)  ? 7.0f  : (float)(i + 1);
            float d30 = (i >= 29) ? 30.0f : (float)(i + 1);
            float d90 = (float)(i + 1);   // for i<=89: windowed at i==89 gives /90 == i+1
            float* o = oc + (size_t)i * (4 * NF);
            o[0]      = v;
            o[NF]     = s7  / d7;
            o[2 * NF] = s30 / d30;
            o[3 * NF] = s90 / d90;
        }
        // entering fast loop at i == 90: s90 == sum x[0..89], s7 == x[84..89]+..., correct state
    }

    // Fast path: steady-state sliding windows, constant reciprocals.
    #pragma unroll 4
    for (; i < end; i++) {
        float v   = xc[(size_t)i * NF];
        float v7  = xc[(size_t)(i - 7)  * NF];
        float v30 = xc[(size_t)(i - 30) * NF];
        float v90 = xc[(size_t)(i - 90) * NF];
        s7  += v - v7;
        s30 += v - v30;
        s90 += v - v90;
        float* o = oc + (size_t)i * (4 * NF);
        o[0]      = v;
        o[NF]     = s7  * inv7;
        o[2 * NF] = s30 * inv30;
        o[3 * NF] = s90 * inv90;
    }
}

extern "C" void kernel_launch(void* const* d_in, const int* in_sizes, int n_in,
                              void* d_out, int out_size) {
    const float* x  = (const float*)d_in[0];
    float*      out = (float*)d_out;
    // T_TOTAL rows, ROWS per thread-tile, TILES_PER_BLOCK tiles per block
    int n_tiles = T_TOTAL / ROWS;                    // 1024
    int n_blocks = n_tiles / TILES_PER_BLOCK;        // 256
    ma_kernel<<<n_blocks, 256>>>(x, out);
}

// round 3
// speedup vs baseline: 1.9393x; 1.9393x over previous
#include <cuda_runtime.h>

#define T_TOTAL 262144
#define NF 64
#define ROWS 64
#define TILES_PER_BLOCK 4

__global__ void __launch_bounds__(256, 8)
ma_kernel(const float* __restrict__ x, float* __restrict__ out) {
    const int t    = threadIdx.x;
    const int f    = t & (NF - 1);
    const int tile = blockIdx.x * TILES_PER_BLOCK + (t >> 6);
    const int r0   = tile * ROWS;

    const float* xc = x + f;
    float*       oc = out + f;

    float s7 = 0.f, s30 = 0.f, s90 = 0.f;

    // Initialize running window sums from up to 90 halo rows above this tile.
    // Rows before t=0 are implicit zeros (clamp halo depth to r0).
    {
        int kmax = (r0 < 90) ? r0 : 90;
        #pragma unroll 6
        for (int k = 1; k <= kmax; k++) {
            float v = xc[(r0 - k) * NF];
            s90 += v;
            if (k <= 30) s30 += v;
            if (k <= 7)  s7  += v;
        }
    }

    const float inv7  = 1.0f / 7.0f;
    const float inv30 = 1.0f / 30.0f;
    const float inv90 = 1.0f / 90.0f;

    int i   = r0;
    const int end = r0 + ROWS;

    if (r0 < 90) {
        // Careful region: rows < 90 need expanding-mean divisors and
        // zero-padded lags. Only tiles 0 and 1 ever run any of this.
        int cend = (end < 90) ? end : 90;
        for (; i < cend; i++) {
            float v = xc[i * NF];
            s7 += v; s30 += v; s90 += v;
            if (i >= 7)  s7  -= xc[(i - 7)  * NF];
            if (i >= 30) s30 -= xc[(i - 30) * NF];
            // i >= 90 never happens in this region
            float d7  = (i >= 6)  ? 7.0f  : (float)(i + 1);
            float d30 = (i >= 29) ? 30.0f : (float)(i + 1);
            float d90 = (float)(i + 1);   // i<=89: at i==89 windowed /90 == i+1
            float* o = oc + i * (4 * NF);
            o[0]      = v;
            o[NF]     = s7  / d7;
            o[2 * NF] = s30 / d30;
            o[3 * NF] = s90 / d90;
        }
    }

    // Fast path: steady-state sliding windows, constant reciprocals.
    #pragma unroll 4
    for (; i < end; i++) {
        float v   = xc[i * NF];
        float v7  = xc[(i - 7)  * NF];
        float v30 = xc[(i - 30) * NF];
        float v90 = xc[(i - 90) * NF];
        s7  += v - v7;
        s30 += v - v30;
        s90 += v - v90;
        float* o = oc + i * (4 * NF);
        o[0]      = v;
        o[NF]     = s7  * inv7;
        o[2 * NF] = s30 * inv30;
        o[3 * NF] = s90 * inv90;
    }
}

extern "C" void kernel_launch(void* const* d_in, const int* in_sizes, int n_in,
                              void* d_out, int out_size) {
    const float* x  = (const float*)d_in[0];
    float*      out = (float*)d_out;
    int n_tiles  = T_TOTAL / ROWS;              // 4096
    int n_blocks = n_tiles / TILES_PER_BLOCK;   // 1024
    ma_kernel<<<n_blocks, 256>>>(x, out);
}

// round 4
// speedup vs baseline: 2.4619x; 1.2695x over previous
#include <cuda_runtime.h>

#define T_TOTAL 262144
#define NF 64
#define NF2 (NF / 2)          // row stride in float2 for x
#define OUTF2 (4 * NF / 2)    // row stride in float2 for out
#define ROWS 32
#define WARPS_PER_BLOCK 8

__device__ __forceinline__ float2 f2add(float2 a, float2 b) {
    return make_float2(a.x + b.x, a.y + b.y);
}
__device__ __forceinline__ float2 f2sub(float2 a, float2 b) {
    return make_float2(a.x - b.x, a.y - b.y);
}
__device__ __forceinline__ float2 f2scale(float2 a, float s) {
    return make_float2(a.x * s, a.y * s);
}

__global__ void __launch_bounds__(256, 6)
ma_kernel(const float* __restrict__ x, float* __restrict__ out) {
    const int t    = threadIdx.x;
    const int lane = t & 31;                       // column-pair index 0..31
    const int warp = t >> 5;
    const int tile = blockIdx.x * WARPS_PER_BLOCK + warp;
    const int r0   = tile * ROWS;

    const float2* xc = (const float2*)x + lane;    // stride NF2 per row
    float2*       oc = (float2*)out + lane;        // stride OUTF2 per row

    float2 s7  = make_float2(0.f, 0.f);
    float2 s30 = make_float2(0.f, 0.f);
    float2 s90 = make_float2(0.f, 0.f);

    // Halo: up to 90 rows above this tile (rows <0 are implicit zeros).
    {
        int kmax = (r0 < 90) ? r0 : 90;
        #pragma unroll 6
        for (int k = 1; k <= kmax; k++) {
            float2 v = xc[(r0 - k) * NF2];
            s90 = f2add(s90, v);
            if (k <= 30) s30 = f2add(s30, v);
            if (k <= 7)  s7  = f2add(s7, v);
        }
    }

    const float inv7  = 1.0f / 7.0f;
    const float inv30 = 1.0f / 30.0f;
    const float inv90 = 1.0f / 90.0f;

    int i = r0;
    const int end = r0 + ROWS;

    if (r0 < 90) {
        // Careful region (rows < 90): expanding-mean divisors, zero-padded lags.
        // Only tiles 0..2 run any of this.
        int cend = (end < 90) ? end : 90;
        for (; i < cend; i++) {
            float2 v = xc[i * NF2];
            s7 = f2add(s7, v); s30 = f2add(s30, v); s90 = f2add(s90, v);
            if (i >= 7)  s7  = f2sub(s7,  xc[(i - 7)  * NF2]);
            if (i >= 30) s30 = f2sub(s30, xc[(i - 30) * NF2]);
            float r7  = (i >= 6)  ? inv7  : 1.0f / (float)(i + 1);
            float r30 = (i >= 29) ? inv30 : 1.0f / (float)(i + 1);
            float r90 = 1.0f / (float)(i + 1);  // i<=89; at i==89 windowed /90 == /(i+1)
            float2* o = oc + i * OUTF2;
            __stcs(o,           v);
            __stcs(o + NF2,     f2scale(s7,  r7));
            __stcs(o + 2 * NF2, f2scale(s30, r30));
            __stcs(o + 3 * NF2, f2scale(s90, r90));
        }
    }

    // Fast path: steady-state sliding windows.
    #pragma unroll 4
    for (; i < end; i++) {
        float2 v   = xc[i * NF2];
        float2 v7  = xc[(i - 7)  * NF2];
        float2 v30 = xc[(i - 30) * NF2];
        float2 v90 = xc[(i - 90) * NF2];
        s7  = f2add(s7,  f2sub(v, v7));
        s30 = f2add(s30, f2sub(v, v30));
        s90 = f2add(s90, f2sub(v, v90));
        float2* o = oc + i * OUTF2;
        __stcs(o,           v);
        __stcs(o + NF2,     f2scale(s7,  inv7));
        __stcs(o + 2 * NF2, f2scale(s30, inv30));
        __stcs(o + 3 * NF2, f2scale(s90, inv90));
    }
}

extern "C" void kernel_launch(void* const* d_in, const int* in_sizes, int n_in,
                              void* d_out, int out_size) {
    const float* x  = (const float*)d_in[0];
    float*      out = (float*)d_out;
    int n_tiles  = T_TOTAL / ROWS;                  // 8192
    int n_blocks = n_tiles / WARPS_PER_BLOCK;       // 1024
    ma_kernel<<<n_blocks, 256>>>(x, out);
}